// round 10
// baseline (speedup 1.0000x reference)
#include <cuda_runtime.h>
#include <cstdint>

#define IN_C   64
#define OUT_C  64
#define KMAX   27
#define MAX_E  2000000
#define BATCH  16
#define PADCAP (MAX_E + KMAX * BATCH + BATCH)

// weight smem layout: [k][c][g][d] -> per-c row is 64 contiguous floats.
// Warp read (lanes = h*16 + gs*4 + dq, offset gs*16+dq*4) hits 8 distinct
// float4 per 8-lane sub-request = conflict-free, no padding needed.
#define WKS  1024                 // floats per k
#define WTOT (KMAX * WKS)         // 27648 floats = 110592 B

// ---- scratch (device globals; no allocation allowed) ----
__device__ int g_hist[KMAX];
__device__ int g_cursor[KMAX];
__device__ int g_sorted[PADCAP];   // packed: eid | (k << 24); -1 = sentinel

// ---- f32x2 helpers (packed fp32, 2 FMA/instr) ----
__device__ __forceinline__ unsigned long long pack_dup(float x) {
    unsigned long long r; unsigned xi = __float_as_uint(x);
    asm("mov.b64 %0, {%1, %1};" : "=l"(r) : "r"(xi));
    return r;
}
__device__ __forceinline__ unsigned long long fma2(unsigned long long a,
                                                   unsigned long long b,
                                                   unsigned long long c) {
    unsigned long long d;
    asm("fma.rn.f32x2 %0, %1, %2, %3;" : "=l"(d) : "l"(a), "l"(b), "l"(c));
    return d;
}
__device__ __forceinline__ void unpack2(unsigned long long v, float& lo, float& hi) {
    asm("mov.b64 {%0, %1}, %2;" : "=f"(lo), "=f"(hi) : "l"(v));
}

// ---- 1) fused: out = bias, g_sorted = -1, block-aggregated k histogram ----
__global__ void init_all(float4* __restrict__ out, const float* __restrict__ bias,
                         const int* __restrict__ ka, int n4, int preN, int E) {
    __shared__ float4 b4[16];
    __shared__ int h[KMAX];
    if (threadIdx.x < 16) b4[threadIdx.x] = reinterpret_cast<const float4*>(bias)[threadIdx.x];
    if (threadIdx.x < KMAX) h[threadIdx.x] = 0;
    __syncthreads();
    int idx = blockIdx.x * blockDim.x + threadIdx.x;
    if (idx < n4)   out[idx] = b4[idx & 15];
    if (idx < preN) g_sorted[idx] = -1;
    if (idx < E)    atomicAdd(&h[ka[idx]], 1);
    __syncthreads();
    if (threadIdx.x < KMAX && h[threadIdx.x]) atomicAdd(&g_hist[threadIdx.x], h[threadIdx.x]);
}

// ---- 2) warp exclusive scan of BATCH-aligned bucket sizes; clears g_hist ----
__global__ void scan_k() {
    int lane = threadIdx.x;
    int v = (lane < KMAX) ? ((g_hist[lane] + BATCH - 1) & ~(BATCH - 1)) : 0;
    int s = v;
    #pragma unroll
    for (int o = 1; o < 32; o <<= 1) {
        int t = __shfl_up_sync(0xffffffffu, s, o);
        if (lane >= o) s += t;
    }
    if (lane < KMAX) {
        g_cursor[lane] = s - v;   // exclusive, aligned starts
        g_hist[lane] = 0;         // reset for next graph replay
    }
}

// ---- 3) scatter packed (eid | k<<24) into k-sorted order ----
__global__ void scatter_k(const int* __restrict__ ka, int E) {
    __shared__ int cnt[KMAX];
    __shared__ int bas[KMAX];
    int idx = blockIdx.x * blockDim.x + threadIdx.x;
    if (threadIdx.x < KMAX) cnt[threadIdx.x] = 0;
    __syncthreads();
    int kv = 0, my = 0;
    bool v = idx < E;
    if (v) { kv = ka[idx]; my = atomicAdd(&cnt[kv], 1); }
    __syncthreads();
    if (threadIdx.x < KMAX && cnt[threadIdx.x])
        bas[threadIdx.x] = atomicAdd(&g_cursor[threadIdx.x], cnt[threadIdx.x]);
    __syncthreads();
    if (v) g_sorted[bas[kv] + my] = idx | (kv << 24);
}

// ---- 4) fused conv: 16-edge batch as two 8-edge sub-batches ----
// Sub-batching halves the live register footprint (acc[4]+xq[4] instead of
// acc[8]+xq[8]) -> ~75 regs -> 768 threads / 24 warps per SM without spill.
// Lane = h*16 + gs*4 + dq: within a sub-batch, half h covers 4 edges.
__global__ __launch_bounds__(768, 1) void conv_k(
    const float* __restrict__ x, const int* __restrict__ ia,
    const int* __restrict__ ja,
    const float* __restrict__ wgt, float* __restrict__ out, int nB)
{
    extern __shared__ float sw[];

    // cooperative weight load: src coalesced; dst = k*1024 + c*64 + g*16 + d
    for (int idx = threadIdx.x; idx < WTOT; idx += blockDim.x) {
        int k = idx % KMAX;
        int r = idx / KMAX;          // r = (g*16+c)*16 + d
        int d = r & 15;
        int c = (r >> 4) & 15;
        int g = r >> 8;
        sw[k * WKS + c * 64 + g * 16 + d] = wgt[idx];
    }
    __syncthreads();

    int lane = threadIdx.x & 31;
    int warp = threadIdx.x >> 5;
    int dq = lane & 3;
    int gs = (lane >> 2) & 3;
    int h  = lane >> 4;

    int nw = gridDim.x * (blockDim.x >> 5);

    #pragma unroll 1
    for (int b = blockIdx.x * (blockDim.x >> 5) + warp; b < nB; b += nw) {
        int base = b * BATCH;

        // lanes 0..15 hold packed edge (base+lane) metadata
        int pk = -1;
        if (lane < BATCH) pk = g_sorted[base + lane];
        int p0 = __shfl_sync(0xffffffffu, pk, 0);
        int kb = (p0 < 0) ? 0 : (p0 >> 24);         // batch-uniform k (0 for dead tail)

        int jj = 0, ii = 0;
        if (pk >= 0) {
            int eid = pk & 0x00FFFFFF;
            jj = ja[eid];
            ii = ia[eid];
        }

        const float* wp = sw + kb * WKS + gs * 16 + dq * 4;

        #pragma unroll
        for (int sb = 0; sb < 2; sb++) {
            // this lane's 4 edge rows of sub-batch sb (half h) + validity mask
            int jr[4];
            unsigned vm = 0;
            #pragma unroll
            for (int t = 0; t < 4; t++) {
                int src = sb * 8 + h * 4 + t;
                jr[t] = __shfl_sync(0xffffffffu, jj, src);
                int ev = __shfl_sync(0xffffffffu, pk, src);
                if (ev >= 0) vm |= (1u << t);
            }

            ulonglong2 acc[4];
            #pragma unroll
            for (int t = 0; t < 4; t++) { acc[t].x = 0ull; acc[t].y = 0ull; }

            #pragma unroll
            for (int cq = 0; cq < 4; cq++) {
                float4 xq[4];
                #pragma unroll
                for (int t = 0; t < 4; t++) {
                    float4 v = make_float4(0.f, 0.f, 0.f, 0.f);
                    if (vm & (1u << t))
                        v = *(const float4*)(x + (size_t)jr[t] * IN_C + gs * 16 + cq * 4);
                    xq[t] = v;
                }
                #pragma unroll
                for (int cc = 0; cc < 4; cc++) {
                    int c = cq * 4 + cc;
                    ulonglong2 wv = *(const ulonglong2*)(wp + c * 64);  // conflict-free LDS.128
                    #pragma unroll
                    for (int t = 0; t < 4; t++) {
                        float xs = (cc == 0) ? xq[t].x : (cc == 1) ? xq[t].y
                                 : (cc == 2) ? xq[t].z : xq[t].w;
                        unsigned long long xd = pack_dup(xs);
                        acc[t].x = fma2(xd, wv.x, acc[t].x);
                        acc[t].y = fma2(xd, wv.y, acc[t].y);
                    }
                }
            }

            // epilogue: one RED.128 per (lane, edge); 2 edges per warp instr
            #pragma unroll
            for (int t = 0; t < 4; t++) {
                int ie = __shfl_sync(0xffffffffu, ii, sb * 8 + h * 4 + t);
                if (vm & (1u << t)) {
                    float a0, a1, a2, a3;
                    unpack2(acc[t].x, a0, a1);
                    unpack2(acc[t].y, a2, a3);
                    atomicAdd(reinterpret_cast<float4*>(out + (size_t)ie * OUT_C + gs * 16 + dq * 4),
                              make_float4(a0, a1, a2, a3));
                }
            }
        }
    }
}

extern "C" void kernel_launch(void* const* d_in, const int* in_sizes, int n_in,
                              void* d_out, int out_size) {
    const float* x    = (const float*)d_in[0];
    const int*   ia   = (const int*)d_in[1];
    const int*   ja   = (const int*)d_in[2];
    const int*   ka   = (const int*)d_in[3];
    // d_in[4] = n (scalar), unused: derive from sizes
    const float* wgt  = (const float*)d_in[5];
    const float* bias = (const float*)d_in[6];
    float*       out  = (float*)d_out;

    int n = in_sizes[0] / IN_C;
    int E = in_sizes[1];
    if (E > MAX_E) E = MAX_E;

    int n4   = n * (OUT_C / 4);
    int preN = E + KMAX * BATCH;                 // sentinel prefill range
    int nB   = (preN + BATCH - 1) / BATCH;
    if (nB * BATCH > preN) preN = nB * BATCH;

    int initN = (n4 > preN) ? n4 : preN;
    if (E > initN) initN = E;
    init_all<<<(initN + 255) / 256, 256>>>((float4*)out, bias, ka, n4, preN, E);
    scan_k<<<1, 32>>>();
    scatter_k<<<(E + 255) / 256, 256>>>(ka, E);

    cudaFuncSetAttribute(conv_k, cudaFuncAttributeMaxDynamicSharedMemorySize,
                         WTOT * 4);
    conv_k<<<148, 768, WTOT * 4>>>(x, ia, ja, wgt, out, nB);
}

// round 11
// speedup vs baseline: 1.6355x; 1.6355x over previous
#include <cuda_runtime.h>
#include <cstdint>

#define IN_C   64
#define OUT_C  64
#define KMAX   27
#define MAX_E  2000000
#define BATCH  16
#define PADCAP (MAX_E + KMAX * BATCH + BATCH)

// weight smem layout: [k][c][g][d] -> per-c row is 64 contiguous floats.
// Warp read (lanes = h*16 + gs*4 + dq, offset gs*16+dq*4) hits 8 distinct
// float4 per 8-lane sub-request = conflict-free, no padding needed.
#define WKS  1024                 // floats per k
#define WTOT (KMAX * WKS)         // 27648 floats = 110592 B

#define NTHR 576                  // 18 warps/SM; reg budget 112 (> ~92 natural)

// ---- scratch (device globals; no allocation allowed) ----
__device__ int g_hist[KMAX];
__device__ int g_cursor[KMAX];
__device__ int g_sorted[PADCAP];   // packed: eid | (k << 24); -1 = sentinel

// ---- f32x2 helpers (packed fp32, 2 FMA/instr) ----
__device__ __forceinline__ unsigned long long pack_dup(float x) {
    unsigned long long r; unsigned xi = __float_as_uint(x);
    asm("mov.b64 %0, {%1, %1};" : "=l"(r) : "r"(xi));
    return r;
}
__device__ __forceinline__ unsigned long long fma2(unsigned long long a,
                                                   unsigned long long b,
                                                   unsigned long long c) {
    unsigned long long d;
    asm("fma.rn.f32x2 %0, %1, %2, %3;" : "=l"(d) : "l"(a), "l"(b), "l"(c));
    return d;
}
__device__ __forceinline__ void unpack2(unsigned long long v, float& lo, float& hi) {
    asm("mov.b64 {%0, %1}, %2;" : "=f"(lo), "=f"(hi) : "l"(v));
}

// ---- 1) fused: out = bias, g_sorted = -1, block-aggregated k histogram ----
__global__ void init_all(float4* __restrict__ out, const float* __restrict__ bias,
                         const int* __restrict__ ka, int n4, int preN, int E) {
    __shared__ float4 b4[16];
    __shared__ int h[KMAX];
    if (threadIdx.x < 16) b4[threadIdx.x] = reinterpret_cast<const float4*>(bias)[threadIdx.x];
    if (threadIdx.x < KMAX) h[threadIdx.x] = 0;
    __syncthreads();
    int idx = blockIdx.x * blockDim.x + threadIdx.x;
    if (idx < n4)   out[idx] = b4[idx & 15];
    if (idx < preN) g_sorted[idx] = -1;
    if (idx < E)    atomicAdd(&h[ka[idx]], 1);
    __syncthreads();
    if (threadIdx.x < KMAX && h[threadIdx.x]) atomicAdd(&g_hist[threadIdx.x], h[threadIdx.x]);
}

// ---- 2) warp exclusive scan of BATCH-aligned bucket sizes; clears g_hist ----
__global__ void scan_k() {
    int lane = threadIdx.x;
    int v = (lane < KMAX) ? ((g_hist[lane] + BATCH - 1) & ~(BATCH - 1)) : 0;
    int s = v;
    #pragma unroll
    for (int o = 1; o < 32; o <<= 1) {
        int t = __shfl_up_sync(0xffffffffu, s, o);
        if (lane >= o) s += t;
    }
    if (lane < KMAX) {
        g_cursor[lane] = s - v;   // exclusive, aligned starts
        g_hist[lane] = 0;         // reset for next graph replay
    }
}

// ---- 3) scatter packed (eid | k<<24) into k-sorted order ----
__global__ void scatter_k(const int* __restrict__ ka, int E) {
    __shared__ int cnt[KMAX];
    __shared__ int bas[KMAX];
    int idx = blockIdx.x * blockDim.x + threadIdx.x;
    if (threadIdx.x < KMAX) cnt[threadIdx.x] = 0;
    __syncthreads();
    int kv = 0, my = 0;
    bool v = idx < E;
    if (v) { kv = ka[idx]; my = atomicAdd(&cnt[kv], 1); }
    __syncthreads();
    if (threadIdx.x < KMAX && cnt[threadIdx.x])
        bas[threadIdx.x] = atomicAdd(&g_cursor[threadIdx.x], cnt[threadIdx.x]);
    __syncthreads();
    if (v) g_sorted[bas[kv] + my] = idx | (kv << 24);
}

// ---- 4) fused conv (R7-proven structure at 576 threads / 112-reg budget) ----
// Warp batch = 16 edges (k-uniform by construction).
// Lane = h*16 + gs*4 + dq: owns output d-quad dq of group gs for the 8 edges
// of half h. Weights: one LDS.128 per c for the whole warp (256B distinct).
__global__ __launch_bounds__(NTHR, 1) void conv_k(
    const float* __restrict__ x, const int* __restrict__ ia,
    const int* __restrict__ ja,
    const float* __restrict__ wgt, float* __restrict__ out, int nB)
{
    extern __shared__ float sw[];

    // cooperative weight load: src coalesced; dst = k*1024 + c*64 + g*16 + d
    for (int idx = threadIdx.x; idx < WTOT; idx += blockDim.x) {
        int k = idx % KMAX;
        int r = idx / KMAX;          // r = (g*16+c)*16 + d
        int d = r & 15;
        int c = (r >> 4) & 15;
        int g = r >> 8;
        sw[k * WKS + c * 64 + g * 16 + d] = wgt[idx];
    }
    __syncthreads();

    int lane = threadIdx.x & 31;
    int warp = threadIdx.x >> 5;
    int dq = lane & 3;
    int gs = (lane >> 2) & 3;
    int h  = lane >> 4;

    int nw = gridDim.x * (blockDim.x >> 5);

    #pragma unroll 1
    for (int b = blockIdx.x * (blockDim.x >> 5) + warp; b < nB; b += nw) {
        int base = b * BATCH;

        // lanes 0..15 hold packed edge (base+lane) metadata
        int pk = -1;
        if (lane < BATCH) pk = g_sorted[base + lane];
        int p0 = __shfl_sync(0xffffffffu, pk, 0);
        int kb = (p0 < 0) ? 0 : (p0 >> 24);         // batch-uniform k (0 for dead tail)

        int jj = 0, ii = 0;
        if (pk >= 0) {
            int eid = pk & 0x00FFFFFF;
            jj = ja[eid];
            ii = ia[eid];
        }

        const float* wp = sw + kb * WKS + gs * 16 + dq * 4;

        // this lane's 8 edge rows (half h) + validity mask
        int jr[8];
        unsigned vm = 0;
        #pragma unroll
        for (int es = 0; es < 8; es++) {
            int src = h * 8 + es;
            jr[es] = __shfl_sync(0xffffffffu, jj, src);
            int ev  = __shfl_sync(0xffffffffu, pk, src);
            if (ev >= 0) vm |= (1u << es);
        }

        ulonglong2 acc[8];
        #pragma unroll
        for (int es = 0; es < 8; es++) { acc[es].x = 0ull; acc[es].y = 0ull; }

        #pragma unroll
        for (int cq = 0; cq < 4; cq++) {
            // gather x chunks: lane reads [gs*16 + cq*4 .. +3] of each of its 8 rows
            float4 xq[8];
            #pragma unroll
            for (int es = 0; es < 8; es++) {
                float4 v = make_float4(0.f, 0.f, 0.f, 0.f);
                if (vm & (1u << es))
                    v = *(const float4*)(x + (size_t)jr[es] * IN_C + gs * 16 + cq * 4);
                xq[es] = v;
            }
            #pragma unroll
            for (int cc = 0; cc < 4; cc++) {
                int c = cq * 4 + cc;
                ulonglong2 wv = *(const ulonglong2*)(wp + c * 64);  // conflict-free LDS.128
                #pragma unroll
                for (int es = 0; es < 8; es++) {
                    float xs = (cc == 0) ? xq[es].x : (cc == 1) ? xq[es].y
                             : (cc == 2) ? xq[es].z : xq[es].w;
                    unsigned long long xd = pack_dup(xs);
                    acc[es].x = fma2(xd, wv.x, acc[es].x);
                    acc[es].y = fma2(xd, wv.y, acc[es].y);
                }
            }
        }

        // epilogue: one RED.128 per (lane, edge-slot); 2 edges per warp instr
        #pragma unroll
        for (int es = 0; es < 8; es++) {
            int ie = __shfl_sync(0xffffffffu, ii, h * 8 + es);
            if (vm & (1u << es)) {
                float a0, a1, a2, a3;
                unpack2(acc[es].x, a0, a1);
                unpack2(acc[es].y, a2, a3);
                atomicAdd(reinterpret_cast<float4*>(out + (size_t)ie * OUT_C + gs * 16 + dq * 4),
                          make_float4(a0, a1, a2, a3));
            }
        }
    }
}

extern "C" void kernel_launch(void* const* d_in, const int* in_sizes, int n_in,
                              void* d_out, int out_size) {
    const float* x    = (const float*)d_in[0];
    const int*   ia   = (const int*)d_in[1];
    const int*   ja   = (const int*)d_in[2];
    const int*   ka   = (const int*)d_in[3];
    // d_in[4] = n (scalar), unused: derive from sizes
    const float* wgt  = (const float*)d_in[5];
    const float* bias = (const float*)d_in[6];
    float*       out  = (float*)d_out;

    int n = in_sizes[0] / IN_C;
    int E = in_sizes[1];
    if (E > MAX_E) E = MAX_E;

    int n4   = n * (OUT_C / 4);
    int preN = E + KMAX * BATCH;                 // sentinel prefill range
    int nB   = (preN + BATCH - 1) / BATCH;
    if (nB * BATCH > preN) preN = nB * BATCH;

    int initN = (n4 > preN) ? n4 : preN;
    if (E > initN) initN = E;
    init_all<<<(initN + 255) / 256, 256>>>((float4*)out, bias, ka, n4, preN, E);
    scan_k<<<1, 32>>>();
    scatter_k<<<(E + 255) / 256, 256>>>(ka, E);

    cudaFuncSetAttribute(conv_k, cudaFuncAttributeMaxDynamicSharedMemorySize,
                         WTOT * 4);
    conv_k<<<148, NTHR, WTOT * 4>>>(x, ia, ja, wgt, out, nB);
}

// round 13
// speedup vs baseline: 1.7820x; 1.0896x over previous
#include <cuda_runtime.h>
#include <cstdint>

#define IN_C   64
#define OUT_C  64
#define KMAX   27
#define MAX_E  2000000
#define BATCH  16
#define PADCAP (MAX_E + KMAX * BATCH + BATCH)

// weight smem layout: [k][g][c][d]; group stride padded so the per-c LDS.128
// (lanes = h*16 + gs*4 + dq) is conflict-free in each 8-lane sub-request.
// (R7-proven layout, kept to minimize variables.)
#define WGS  272                 // 256 + 16 pad
#define WKS  (4 * WGS)           // 1088
#define WTOT (KMAX * WKS)        // 29376 floats = 117504 B

// ---- scratch (device globals; no allocation allowed) ----
__device__ int g_hist[KMAX];
__device__ int g_cursor[KMAX];
__device__ int g_sorted[PADCAP];   // packed: eid | (k << 24); -1 = sentinel

// ---- f32x2 helpers (packed fp32, 2 FMA/instr) ----
__device__ __forceinline__ unsigned long long pack_dup(float x) {
    unsigned long long r; unsigned xi = __float_as_uint(x);
    asm("mov.b64 %0, {%1, %1};" : "=l"(r) : "r"(xi));
    return r;
}
__device__ __forceinline__ unsigned long long fma2(unsigned long long a,
                                                   unsigned long long b,
                                                   unsigned long long c) {
    unsigned long long d;
    asm("fma.rn.f32x2 %0, %1, %2, %3;" : "=l"(d) : "l"(a), "l"(b), "l"(c));
    return d;
}
__device__ __forceinline__ void unpack2(unsigned long long v, float& lo, float& hi) {
    asm("mov.b64 {%0, %1}, %2;" : "=f"(lo), "=f"(hi) : "l"(v));
}

// ---- 1) fused: out = bias, g_sorted = -1, block-aggregated k histogram ----
__global__ void init_all(float4* __restrict__ out, const float* __restrict__ bias,
                         const int* __restrict__ ka, int n4, int preN, int E) {
    __shared__ float4 b4[16];
    __shared__ int h[KMAX];
    if (threadIdx.x < 16) b4[threadIdx.x] = reinterpret_cast<const float4*>(bias)[threadIdx.x];
    if (threadIdx.x < KMAX) h[threadIdx.x] = 0;
    __syncthreads();
    int idx = blockIdx.x * blockDim.x + threadIdx.x;
    if (idx < n4)   out[idx] = b4[idx & 15];
    if (idx < preN) g_sorted[idx] = -1;
    if (idx < E)    atomicAdd(&h[ka[idx]], 1);
    __syncthreads();
    if (threadIdx.x < KMAX && h[threadIdx.x]) atomicAdd(&g_hist[threadIdx.x], h[threadIdx.x]);
}

// ---- 2) warp exclusive scan of BATCH-aligned bucket sizes; clears g_hist ----
__global__ void scan_k() {
    int lane = threadIdx.x;
    int v = (lane < KMAX) ? ((g_hist[lane] + BATCH - 1) & ~(BATCH - 1)) : 0;
    int s = v;
    #pragma unroll
    for (int o = 1; o < 32; o <<= 1) {
        int t = __shfl_up_sync(0xffffffffu, s, o);
        if (lane >= o) s += t;
    }
    if (lane < KMAX) {
        g_cursor[lane] = s - v;   // exclusive, aligned starts
        g_hist[lane] = 0;         // reset for next graph replay
    }
}

// ---- 3) scatter packed (eid | k<<24) into k-sorted order ----
__global__ void scatter_k(const int* __restrict__ ka, int E) {
    __shared__ int cnt[KMAX];
    __shared__ int bas[KMAX];
    int idx = blockIdx.x * blockDim.x + threadIdx.x;
    if (threadIdx.x < KMAX) cnt[threadIdx.x] = 0;
    __syncthreads();
    int kv = 0, my = 0;
    bool v = idx < E;
    if (v) { kv = ka[idx]; my = atomicAdd(&cnt[kv], 1); }
    __syncthreads();
    if (threadIdx.x < KMAX && cnt[threadIdx.x])
        bas[threadIdx.x] = atomicAdd(&g_cursor[threadIdx.x], cnt[threadIdx.x]);
    __syncthreads();
    if (v) g_sorted[bas[kv] + my] = idx | (kv << 24);
}

// ---- 4) fused conv: R7 structure + double-buffered x loads across cq ----
// Warp batch = 16 edges (k-uniform). Lane = h*16 + gs*4 + dq: owns output
// d-quad dq of group gs for the 8 edges of half h.
// cq round's loads are issued one round ahead so the L2 hit latency overlaps
// this warp's own FMA block instead of stalling it.
__global__ __launch_bounds__(512, 1) void conv_k(
    const float* __restrict__ x, const int* __restrict__ ia,
    const int* __restrict__ ja,
    const float* __restrict__ wgt, float* __restrict__ out, int nB)
{
    extern __shared__ float sw[];

    // cooperative weight load: src coalesced, dst scattered (once per CTA)
    for (int idx = threadIdx.x; idx < IN_C * (OUT_C / 4) * KMAX; idx += blockDim.x) {
        int k = idx % KMAX;
        int r = idx / KMAX;          // r = (g*16+c)*16 + d
        int d = r & 15;
        int c = (r >> 4) & 15;
        int g = r >> 8;
        sw[k * WKS + g * WGS + c * 16 + d] = wgt[idx];
    }
    __syncthreads();

    int lane = threadIdx.x & 31;
    int warp = threadIdx.x >> 5;
    int dq = lane & 3;
    int gs = (lane >> 2) & 3;
    int h  = lane >> 4;

    int nw = gridDim.x * (blockDim.x >> 5);

    #pragma unroll 1
    for (int b = blockIdx.x * (blockDim.x >> 5) + warp; b < nB; b += nw) {
        int base = b * BATCH;

        // lanes 0..15 hold packed edge (base+lane) metadata
        int pk = -1;
        if (lane < BATCH) pk = g_sorted[base + lane];
        int p0 = __shfl_sync(0xffffffffu, pk, 0);
        int kb = (p0 < 0) ? 0 : (p0 >> 24);        // batch-uniform k (0 for dead tail)

        int jj = 0, ii = 0;                         // jj=0 for invalid -> row 0 safe
        if (pk >= 0) {
            int eid = pk & 0x00FFFFFF;
            jj = ja[eid];
            ii = ia[eid];
        }

        const float* wp = sw + kb * WKS + gs * WGS + dq * 4;

        // this lane's 8 edge row base pointers (half h) + validity mask
        const float* xp[8];
        unsigned vm = 0;
        #pragma unroll
        for (int es = 0; es < 8; es++) {
            int src = h * 8 + es;
            int jr  = __shfl_sync(0xffffffffu, jj, src);
            xp[es]  = x + (size_t)jr * IN_C + gs * 16;
            int ev  = __shfl_sync(0xffffffffu, pk, src);
            if (ev >= 0) vm |= (1u << es);
        }

        ulonglong2 acc[8];
        #pragma unroll
        for (int es = 0; es < 8; es++) { acc[es].x = 0ull; acc[es].y = 0ull; }

        // prologue: unconditional loads for cq=0 (invalid lanes read x row 0)
        float4 xA[8], xB[8];
        #pragma unroll
        for (int es = 0; es < 8; es++) xA[es] = *(const float4*)(xp[es] + 0);

        #pragma unroll
        for (int cq = 0; cq < 4; cq++) {
            float4* cur = (cq & 1) ? xB : xA;
            float4* nxt = (cq & 1) ? xA : xB;

            // prefetch next round's x chunks before consuming this round's
            if (cq < 3) {
                #pragma unroll
                for (int es = 0; es < 8; es++)
                    nxt[es] = *(const float4*)(xp[es] + (cq + 1) * 4);
            }

            #pragma unroll
            for (int cc = 0; cc < 4; cc++) {
                int c = cq * 4 + cc;
                ulonglong2 wv = *(const ulonglong2*)(wp + c * 16);  // 1 LDS.128 / warp / c
                #pragma unroll
                for (int es = 0; es < 8; es++) {
                    float xs = (cc == 0) ? cur[es].x : (cc == 1) ? cur[es].y
                             : (cc == 2) ? cur[es].z : cur[es].w;
                    unsigned long long xd = pack_dup(xs);
                    acc[es].x = fma2(xd, wv.x, acc[es].x);
                    acc[es].y = fma2(xd, wv.y, acc[es].y);
                }
            }
        }

        // epilogue: one RED.128 per (lane, edge-slot); 2 edges per warp instr
        #pragma unroll
        for (int es = 0; es < 8; es++) {
            int ie = __shfl_sync(0xffffffffu, ii, h * 8 + es);
            if (vm & (1u << es)) {
                float a0, a1, a2, a3;
                unpack2(acc[es].x, a0, a1);
                unpack2(acc[es].y, a2, a3);
                atomicAdd(reinterpret_cast<float4*>(out + (size_t)ie * OUT_C + gs * 16 + dq * 4),
                          make_float4(a0, a1, a2, a3));
            }
        }
    }
}

extern "C" void kernel_launch(void* const* d_in, const int* in_sizes, int n_in,
                              void* d_out, int out_size) {
    const float* x    = (const float*)d_in[0];
    const int*   ia   = (const int*)d_in[1];
    const int*   ja   = (const int*)d_in[2];
    const int*   ka   = (const int*)d_in[3];
    // d_in[4] = n (scalar), unused: derive from sizes
    const float* wgt  = (const float*)d_in[5];
    const float* bias = (const float*)d_in[6];
    float*       out  = (float*)d_out;

    int n = in_sizes[0] / IN_C;
    int E = in_sizes[1];
    if (E > MAX_E) E = MAX_E;

    int n4   = n * (OUT_C / 4);
    int preN = E + KMAX * BATCH;                 // sentinel prefill range
    int nB   = (preN + BATCH - 1) / BATCH;
    if (nB * BATCH > preN) preN = nB * BATCH;

    int initN = (n4 > preN) ? n4 : preN;
    if (E > initN) initN = E;
    init_all<<<(initN + 255) / 256, 256>>>((float4*)out, bias, ka, n4, preN, E);
    scan_k<<<1, 32>>>();
    scatter_k<<<(E + 255) / 256, 256>>>(ka, E);

    cudaFuncSetAttribute(conv_k, cudaFuncAttributeMaxDynamicSharedMemorySize,
                         WTOT * 4);
    conv_k<<<148, 512, WTOT * 4>>>(x, ia, ja, wgt, out, nB);
}